// round 7
// baseline (speedup 1.0000x reference)
#include <cuda_runtime.h>
#include <cstdint>

typedef unsigned long long u64;

#define NIMG   16
#define NBOX   25200
#define NCH    85
#define NC     80
#define NBINS  4096
#define CAP    4096
#define TOPK_N 1000
#define MAXDET 300
#define CONF   0.25f
#define IOU_T  0.45f
#define MAXWH  4096.0f
#define PREBIN 3686                 // bin of score 0.89998169 (bits 0x3F666000)
#define PRE_F  __uint_as_float(0x3F666000u)
#define PRECAP 24576

// ---------------- scratch (static device memory) ----------------
__device__ int g_precnt[NIMG];      // zero-initialized; reset by k_final each call
__device__ int g_T[NIMG];
__device__ int g_ok[NIMG];
__device__ u64 g_pre[NIMG][PRECAP];

// ---------------- kernel 1: prefilter pass (warp-per-box, obj-gated) ----------------
// collect (box,cls) with obj > CONF and score >= PRE_F as sortable keys
__global__ void k_pre(const float* __restrict__ x) {
    int b = blockIdx.y;
    int lane = threadIdx.x & 31;
    int gw = blockIdx.x * (blockDim.x >> 5) + (threadIdx.x >> 5);
    int W = gridDim.x * (blockDim.x >> 5);
    const float* xb = x + (size_t)b * NBOX * NCH;

    for (int box = gw; box < NBOX; box += W) {
        const float* p = xb + (size_t)box * NCH;
        float obj = p[4];                     // warp-uniform broadcast load
        if (obj <= CONF) continue;            // skip: class probs never read
        #pragma unroll
        for (int r = 0; r < 3; r++) {
            int c = r * 32 + lane;
            bool pre = false; unsigned bits = 0;
            if (c < NC) {
                float s = __fmul_rn(p[5 + c], obj);
                bits = __float_as_uint(s);
                pre = (s >= PRE_F);           // implies s > CONF; positive floats
            }
            unsigned m = __ballot_sync(0xffffffffu, pre);
            if (m) {
                int leader = __ffs(m) - 1;
                int basep = 0;
                if (lane == leader) basep = atomicAdd(&g_precnt[b], __popc(m));
                basep = __shfl_sync(0xffffffffu, basep, leader);
                if (pre) {
                    int pos = basep + __popc(m & ((1u << lane) - 1u));
                    if (pos < PRECAP) {
                        unsigned ent = (unsigned)(box * NC + c);
                        g_pre[b][pos] = ((u64)bits << 32) | (u64)(0xFFFFFFFFu - ent);
                    }
                }
            }
        }
    }
}

// ---------------- kernel 2: exact threshold (happy: from pre-list; else full scan) ----------------
__global__ void k_check(const float* __restrict__ x) {
    int b = blockIdx.x;
    int tid = threadIdx.x;                    // 512 threads
    __shared__ int sh[NBINS];
    __shared__ int sT;
    int pn_raw = g_precnt[b];
    bool ok0 = (pn_raw >= TOPK_N) && (pn_raw <= PRECAP);

    if (ok0) {
        // window histogram over bins [PREBIN, PREBIN+512) from the pre-list
        sh[tid] = 0;
        __syncthreads();
        for (int i = tid; i < pn_raw; i += 512) {
            unsigned bits = (unsigned)(g_pre[b][i] >> 32);
            int rel = (int)(bits >> 12) - (0x3E800 + PREBIN);
            atomicAdd(&sh[min(max(rel, 0), 511)], 1);
        }
        __syncthreads();
        // suffix scan over 512
        for (int off = 1; off < 512; off <<= 1) {
            int v = (tid + off < 512) ? sh[tid + off] : 0;
            __syncthreads();
            sh[tid] += v;
            __syncthreads();
        }
        if (tid == 0) sT = 0;
        __syncthreads();
        if (sh[tid] >= TOPK_N && (tid == 511 || sh[tid + 1] < TOPK_N)) sT = tid;
        __syncthreads();
        if (tid == 0) { g_T[b] = PREBIN + sT; g_ok[b] = 1; }
    } else {
        // FALLBACK (exact, slow; never taken on typical inputs): full histogram of image b
        for (int i = tid; i < NBINS; i += 512) sh[i] = 0;
        __syncthreads();
        int lane = tid & 31, warp = tid >> 5;
        const float* xb = x + (size_t)b * NBOX * NCH;
        for (int box = warp; box < NBOX; box += 16) {
            const float* p = xb + (size_t)box * NCH;
            float obj = p[4];
            if (obj <= CONF) continue;
            #pragma unroll
            for (int r = 0; r < 3; r++) {
                int c = r * 32 + lane;
                if (c < NC) {
                    float s = __fmul_rn(p[5 + c], obj);
                    if (s > CONF) {
                        int bin = (int)(__float_as_uint(s) >> 12) - 0x3E800;
                        atomicAdd(&sh[min(max(bin, 0), NBINS - 1)], 1);
                    }
                }
            }
        }
        __syncthreads();
        // suffix scan over 4096 (8 per thread)
        for (int off = 1; off < NBINS; off <<= 1) {
            int v[NBINS / 512];
            #pragma unroll
            for (int k = 0; k < NBINS / 512; k++) {
                int i = tid + k * 512;
                int j = i + off;
                v[k] = (j < NBINS) ? sh[j] : 0;
            }
            __syncthreads();
            #pragma unroll
            for (int k = 0; k < NBINS / 512; k++) sh[tid + k * 512] += v[k];
            __syncthreads();
        }
        if (tid == 0) sT = 0;
        __syncthreads();
        #pragma unroll
        for (int k = 0; k < NBINS / 512; k++) {
            int i = tid + k * 512;
            if (sh[i] >= TOPK_N && (i == NBINS - 1 || sh[i + 1] < TOPK_N)) sT = i;
        }
        __syncthreads();
        if (tid == 0) { g_T[b] = sT; g_ok[b] = 0; }
    }
}

// ---------------- kernel 3: fused select + sort + gather + per-class NMS + output ----------------
#define OFF_KEY   0                         // u64[4096]          32768
#define OFF_OFFB  32768                     // float4[1024]       16384
#define OFF_SELB  49152                     // float4[1024]       16384
#define OFF_SCORE 65536                     // float[1024]         4096
#define OFF_KEEP  69632                     // int[1024]           4096
#define OFF_CLS   73728                     // ushort[1024]        2048
#define OFF_LIST  75776                     // ushort[1024]        2048
#define OFF_CCNT  77824                     // int[80]              320
#define OFF_COFF  78144                     // int[80]              320
#define OFF_WSUM  78464                     // int[32]              128
#define SMEM_FINAL 78592

__global__ void k_final(const float* __restrict__ x, float* __restrict__ out) {
    extern __shared__ unsigned char sm[];
    u64*            key  = (u64*)(sm + OFF_KEY);
    float4*         offb = (float4*)(sm + OFF_OFFB);
    float4*         selb = (float4*)(sm + OFF_SELB);
    float*          scr  = (float*)(sm + OFF_SCORE);
    int*            keep = (int*)(sm + OFF_KEEP);
    unsigned short* cls  = (unsigned short*)(sm + OFF_CLS);
    unsigned short* list = (unsigned short*)(sm + OFF_LIST);
    int*            ccnt = (int*)(sm + OFF_CCNT);
    int*            coff = (int*)(sm + OFF_COFF);
    int*            wsum = (int*)(sm + OFF_WSUM);
    __shared__ int cnt_s;

    int b = blockIdx.x;
    int tid = threadIdx.x;                  // 0..1023
    int lane = tid & 31, warp = tid >> 5;
    const float* xb = x + (size_t)b * NBOX * NCH;

    // zero output rows for this image (replaces k_zero)
    for (int i = tid; i < MAXDET * 6; i += 1024) out[(size_t)b * MAXDET * 6 + i] = 0.0f;

    for (int i = tid; i < CAP; i += 1024) key[i] = 0ULL;
    if (tid == 0) cnt_s = 0;
    __syncthreads();

    int T = g_T[b];
    if (g_ok[b]) {
        // ---- select from prefilter list with bin >= T ----
        int pn = min(g_precnt[b], PRECAP);
        for (int i0 = 0; i0 < pn; i0 += 1024) {
            int i = i0 + tid;
            bool take = false; u64 kk = 0;
            if (i < pn) {
                kk = g_pre[b][i];
                take = ((int)(kk >> 44) - 0x3E800) >= T;
            }
            unsigned m = __ballot_sync(0xffffffffu, take);
            if (m) {
                int leader = __ffs(m) - 1;
                int basep = 0;
                if (lane == leader) basep = atomicAdd(&cnt_s, __popc(m));
                basep = __shfl_sync(0xffffffffu, basep, leader);
                if (take) {
                    int pos = basep + __popc(m & ((1u << lane) - 1u));
                    if (pos < CAP) key[pos] = kk;
                }
            }
        }
    } else {
        // ---- FALLBACK: full-image compact (warp-per-box, 32 warps) ----
        for (int box = warp; box < NBOX; box += 32) {
            const float* p = xb + (size_t)box * NCH;
            float obj = p[4];
            if (obj <= CONF) continue;
            #pragma unroll
            for (int r = 0; r < 3; r++) {
                int c = r * 32 + lane;
                bool take = false; unsigned bits = 0;
                if (c < NC) {
                    float s = __fmul_rn(p[5 + c], obj);
                    if (s > CONF) {
                        bits = __float_as_uint(s);
                        int bin = min(max((int)(bits >> 12) - 0x3E800, 0), NBINS - 1);
                        take = (bin >= T);
                    }
                }
                unsigned m = __ballot_sync(0xffffffffu, take);
                if (m) {
                    int leader = __ffs(m) - 1;
                    int basep = 0;
                    if (lane == leader) basep = atomicAdd(&cnt_s, __popc(m));
                    basep = __shfl_sync(0xffffffffu, basep, leader);
                    if (take) {
                        int pos = basep + __popc(m & ((1u << lane) - 1u));
                        if (pos < CAP) {
                            unsigned ent = (unsigned)(box * NC + c);
                            key[pos] = ((u64)bits << 32) | (u64)(0xFFFFFFFFu - ent);
                        }
                    }
                }
            }
        }
    }
    __syncthreads();
    int cnt = min(cnt_s, CAP);
    unsigned npow = (cnt <= 1024) ? 1024u : ((cnt <= 2048) ? 2048u : 4096u);

    // ---- bitonic sort descending (key = score_bits:~idx == top_k order) ----
    for (unsigned k = 2; k <= npow; k <<= 1) {
        for (unsigned j = k >> 1; j > 0; j >>= 1) {
            for (unsigned i = tid; i < npow; i += 1024) {
                unsigned ixj = i ^ j;
                if (ixj > i) {
                    u64 a = key[i], c2 = key[ixj];
                    bool descBlock = ((i & k) == 0);
                    if (descBlock ? (a < c2) : (a > c2)) { key[i] = c2; key[ixj] = a; }
                }
            }
            __syncthreads();
        }
    }

    // ---- gather top-1000: boxes, scores, classes ----
    if (tid < TOPK_N) {
        u64 kk = key[tid];
        unsigned bits = (unsigned)(kk >> 32);
        float s, x1, y1, x2, y2, cf; int ci = 0;
        if (bits) {
            unsigned ent = 0xFFFFFFFFu - (unsigned)(kk & 0xFFFFFFFFull);
            int bi = (int)(ent / NC);
            ci = (int)(ent - (unsigned)bi * NC);
            const float* p = xb + (size_t)bi * NCH;
            float cx = p[0], cy = p[1], w = p[2], h = p[3];
            x1 = cx - 0.5f * w;  y1 = cy - 0.5f * h;
            x2 = cx + 0.5f * w;  y2 = cy + 0.5f * h;
            cf = (float)ci;
            s = __uint_as_float(bits);
        } else {
            x1 = y1 = x2 = y2 = 0.f; cf = 0.f; s = 0.f;
        }
        selb[tid] = make_float4(x1, y1, x2, y2);
        scr[tid] = s;
        cls[tid] = (unsigned short)ci;
        float off = cf * MAXWH;
        offb[tid] = make_float4(x1 + off, y1 + off, x2 + off, y2 + off);
    }
    keep[tid] = 0;
    __syncthreads();

    // ---- per-class member lists (stable, ascending rank) ----
    for (int c = warp; c < NC; c += 32) {
        int cc = 0;
        for (int ch = 0; ch < 32; ch++) {
            int t = ch * 32 + lane;
            bool mem = (t < TOPK_N) && (scr[t] > 0.0f) && ((int)cls[t] == c);
            cc += __popc(__ballot_sync(0xffffffffu, mem));
        }
        if (lane == 0) ccnt[c] = cc;
    }
    __syncthreads();
    if (tid == 0) { int a = 0; for (int c = 0; c < NC; c++) { coff[c] = a; a += ccnt[c]; } }
    __syncthreads();
    for (int c = warp; c < NC; c += 32) {
        int p = coff[c];
        for (int ch = 0; ch < 32; ch++) {
            int t = ch * 32 + lane;
            bool mem = (t < TOPK_N) && (scr[t] > 0.0f) && ((int)cls[t] == c);
            unsigned m = __ballot_sync(0xffffffffu, mem);
            if (mem) list[p + __popc(m & ((1u << lane) - 1u))] = (unsigned short)t;
            p += __popc(m);
        }
    }
    __syncthreads();

    // ---- greedy NMS per class (cross-class IoU is exactly 0 due to MAXWH offset) ----
    for (int c = warp; c < NC; c += 32) {
        int m = ccnt[c], base = coff[c];
        unsigned sup = 0;                  // lane l owns slots q with q%32==l, bit q>>5
        for (int p = 0; p < m; p++) {
            unsigned w = __shfl_sync(0xffffffffu, sup, p & 31);
            if ((w >> (p >> 5)) & 1u) continue;     // pivot suppressed (warp-uniform)
            int tp = list[base + p];
            if (lane == 0) keep[tp] = 1;
            float4 a = offb[tp];
            float aarea = __fmul_rn(__fsub_rn(a.z, a.x), __fsub_rn(a.w, a.y));
            for (int q = lane; q < m; q += 32) {
                if (q > p && !((sup >> (q >> 5)) & 1u)) {
                    float4 cb = offb[list[base + q]];
                    float ix1 = fmaxf(a.x, cb.x);
                    float iy1 = fmaxf(a.y, cb.y);
                    float ix2 = fminf(a.z, cb.z);
                    float iy2 = fminf(a.w, cb.w);
                    float iw = fmaxf(__fsub_rn(ix2, ix1), 0.0f);
                    float ih = fmaxf(__fsub_rn(iy2, iy1), 0.0f);
                    float inter = __fmul_rn(iw, ih);
                    float carea = __fmul_rn(__fsub_rn(cb.z, cb.x), __fsub_rn(cb.w, cb.y));
                    float uni = __fsub_rn(__fadd_rn(aarea, carea), inter);
                    float iou = __fdiv_rn(inter, fmaxf(uni, 1e-9f));
                    if (iou > IOU_T) sup |= 1u << (q >> 5);
                }
            }
        }
    }
    __syncthreads();

    // ---- rank kept entries (block scan) + write output ----
    int flag = (tid < TOPK_N) ? keep[tid] : 0;
    int v = flag;
    #pragma unroll
    for (int o = 1; o < 32; o <<= 1) {
        int u = __shfl_up_sync(0xffffffffu, v, o);
        if (lane >= o) v += u;
    }
    if (lane == 31) wsum[warp] = v;
    __syncthreads();
    if (warp == 0) {
        int ws = wsum[lane];
        #pragma unroll
        for (int o = 1; o < 32; o <<= 1) {
            int u = __shfl_up_sync(0xffffffffu, ws, o);
            if (lane >= o) ws += u;
        }
        wsum[lane] = ws;
    }
    __syncthreads();
    int incl = v + (warp ? wsum[warp - 1] : 0);
    int r = incl - flag;
    if (flag && r < MAXDET) {
        float4 bx = selb[tid];
        float* o = out + ((size_t)b * MAXDET + r) * 6;
        o[0] = bx.x; o[1] = bx.y; o[2] = bx.z; o[3] = bx.w;
        o[4] = scr[tid];
        o[5] = (float)cls[tid];
    }

    // reset prefilter counter for the next graph replay (deterministic)
    __syncthreads();
    if (tid == 0) g_precnt[b] = 0;
}

// ---------------- launch ----------------
extern "C" void kernel_launch(void* const* d_in, const int* in_sizes, int n_in,
                              void* d_out, int out_size) {
    (void)in_sizes; (void)n_in; (void)out_size;
    const float* x = (const float*)d_in[0];
    float* out = (float*)d_out;

    cudaFuncSetAttribute(k_final, cudaFuncAttributeMaxDynamicSharedMemorySize, SMEM_FINAL);

    k_pre<<<dim3(132, NIMG), 256>>>(x);
    k_check<<<NIMG, 512>>>(x);
    k_final<<<NIMG, 1024, SMEM_FINAL>>>(x, out);
}